// round 2
// baseline (speedup 1.0000x reference)
#include <cuda_runtime.h>
#include <cuda_bf16.h>
#include <math.h>

// ---------------------------------------------------------------------------
// Swin Transformer block, fp32. Double-buffered SGEMM mainloop this round.
// B=32, H=W=56, C=384, heads=12, hd=32, window=7, shift=3.
// Tokens T = 100352. Windows Bw = 2048, N = 49.
// ---------------------------------------------------------------------------

#define T_TOK   100352          // B * H * W
#define CDIM    384
#define HID     1536
#define QKVN    1152
#define BW      2048            // B * nW
#define NWIN    49
#define HEADS   12
#define HD      32
#define FULLM   0xffffffffu

// scratch (device globals: allocation-guard-safe)
__device__ float g_xw  [(size_t)T_TOK * CDIM];   // LN1 output, window order
__device__ float g_qkv [(size_t)T_TOK * QKVN];   // qkv
__device__ float g_attn[(size_t)T_TOK * CDIM];   // attention out, window order
__device__ float g_xnew[(size_t)T_TOK * CDIM];   // x + attn branch, natural order
__device__ float g_yn  [(size_t)T_TOK * CDIM];   // LN2 output
__device__ float g_hid [(size_t)T_TOK * HID];    // fc1 output

// window-order row -> natural-order row (fuses roll(-3,-3) + window_partition,
// and equally the inverse window_reverse + roll(+3,+3))
__device__ __forceinline__ int win_to_nat(int rw) {
    int bw = rw / NWIN, n = rw - bw * NWIN;
    int b  = bw >> 6,  w  = bw & 63;
    int wh = w >> 3,   ww = w & 7;
    int r  = n / 7,    c  = n - r * 7;
    int h0 = wh * 7 + r + 3; if (h0 >= 56) h0 -= 56;
    int w0 = ww * 7 + c + 3; if (w0 >= 56) w0 -= 56;
    return b * 3136 + h0 * 56 + w0;
}

// ---------------------------------------------------------------------------
// LayerNorm over C=384. 128 threads, 3 elems/thread.
// GATHER=1: row rw reads natural row win_to_nat(rw)  (LN1 + shift + partition)
// GATHER=0: identity                                (LN2)
// ---------------------------------------------------------------------------
template <int GATHER>
__global__ void ln_kernel(const float* __restrict__ x,
                          const float* __restrict__ w,
                          const float* __restrict__ b,
                          float* __restrict__ out) {
    int rw = blockIdx.x;
    int g  = GATHER ? win_to_nat(rw) : rw;
    const float* xr = x + (size_t)g * CDIM;
    int t = threadIdx.x;

    float v0 = xr[t], v1 = xr[t + 128], v2 = xr[t + 256];
    float s  = v0 + v1 + v2;
    float sq = v0 * v0 + v1 * v1 + v2 * v2;

    #pragma unroll
    for (int o = 16; o; o >>= 1) {
        s  += __shfl_xor_sync(FULLM, s,  o);
        sq += __shfl_xor_sync(FULLM, sq, o);
    }
    __shared__ float ssum[4], ssq[4];
    int warp = t >> 5, lane = t & 31;
    if (!lane) { ssum[warp] = s; ssq[warp] = sq; }
    __syncthreads();
    s  = ssum[0] + ssum[1] + ssum[2] + ssum[3];
    sq = ssq[0]  + ssq[1]  + ssq[2]  + ssq[3];

    float m    = s * (1.0f / CDIM);
    float var  = sq * (1.0f / CDIM) - m * m;
    float rstd = rsqrtf(var + 1e-5f);

    float* o = out + (size_t)rw * CDIM;
    o[t]       = (v0 - m) * rstd * w[t]       + b[t];
    o[t + 128] = (v1 - m) * rstd * w[t + 128] + b[t + 128];
    o[t + 256] = (v2 - m) * rstd * w[t + 256] + b[t + 256];
}

// ---------------------------------------------------------------------------
// SGEMM: C = A[MxK] * B[KxN] (+bias, epilogue). 128x128 tile, BK=8,
// 256 threads, 8x8 per thread, DOUBLE-BUFFERED smem (1 barrier / K-step,
// next tile's LDGs issued before the FMA block to hide L2/DRAM latency).
// Requires M%128==0, N%128==0, K%8==0.
// EPI 0: C = acc + bias                              (qkv)
// EPI 1: C = gelu(acc + bias)                        (fc1)
// EPI 2: C[perm(row)] = resid[perm(row)] + acc+bias  (proj + reverse + residual)
// EPI 3: C[row] = resid[row] + acc + bias            (fc2 + residual)
// ---------------------------------------------------------------------------
template <int EPI>
__global__ __launch_bounds__(256)
void sgemm_kernel(const float* __restrict__ A, const float* __restrict__ B,
                  const float* __restrict__ bias, const float* __restrict__ resid,
                  float* __restrict__ C, int M, int N, int K) {
    __shared__ float As[2][8][128];
    __shared__ float Bs[2][8][132];   // +4 pad: no systematic conflicts on stores

    int bx = blockIdx.x, by = blockIdx.y;
    int tid = threadIdx.x;
    int tx = tid & 15;       // col group (8 cols each)
    int ty = tid >> 4;       // row group (8 rows each)

    const float* Ab = A + (size_t)by * 128 * K;
    const float* Bb = B + (size_t)bx * 128;

    int arow = tid >> 1;            // 0..127
    int acol = (tid & 1) << 2;      // 0 or 4
    int brow = tid >> 5;            // 0..7
    int bcol = (tid & 31) << 2;     // 0..124

    const float* aptr = Ab + (size_t)arow * K + acol;
    const float* bptr = Bb + (size_t)brow * N + bcol;

    float acc[8][8];
    #pragma unroll
    for (int i = 0; i < 8; i++)
        #pragma unroll
        for (int j = 0; j < 8; j++) acc[i][j] = 0.0f;

    // prologue: tile 0 -> buffer 0
    {
        float4 a = *(const float4*)(aptr);
        As[0][acol + 0][arow] = a.x;
        As[0][acol + 1][arow] = a.y;
        As[0][acol + 2][arow] = a.z;
        As[0][acol + 3][arow] = a.w;
        float4 bb = *(const float4*)(bptr);
        *(float4*)&Bs[0][brow][bcol] = bb;
    }
    __syncthreads();

    int buf = 0;
    for (int k0 = 0; k0 < K; k0 += 8) {
        bool more = (k0 + 8) < K;
        float4 na, nb;
        if (more) {        // issue next tile's loads before the FMA block
            na = *(const float4*)(aptr + k0 + 8);
            nb = *(const float4*)(bptr + (size_t)(k0 + 8) * N);
        }

        #pragma unroll
        for (int k = 0; k < 8; k++) {
            float ar[8], br[8];
            *(float4*)&ar[0] = *(const float4*)&As[buf][k][ty * 8];
            *(float4*)&ar[4] = *(const float4*)&As[buf][k][ty * 8 + 4];
            *(float4*)&br[0] = *(const float4*)&Bs[buf][k][tx * 8];
            *(float4*)&br[4] = *(const float4*)&Bs[buf][k][tx * 8 + 4];
            #pragma unroll
            for (int i = 0; i < 8; i++)
                #pragma unroll
                for (int j = 0; j < 8; j++)
                    acc[i][j] = fmaf(ar[i], br[j], acc[i][j]);
        }

        if (more) {
            int nb_ = buf ^ 1;
            As[nb_][acol + 0][arow] = na.x;
            As[nb_][acol + 1][arow] = na.y;
            As[nb_][acol + 2][arow] = na.z;
            As[nb_][acol + 3][arow] = na.w;
            *(float4*)&Bs[nb_][brow][bcol] = nb;
            __syncthreads();
            buf = nb_;
        }
    }

    int row0 = by * 128 + ty * 8;
    int col0 = bx * 128 + tx * 8;
    #pragma unroll
    for (int i = 0; i < 8; i++) {
        int row = row0 + i;
        size_t orow;
        if (EPI == 2) orow = (size_t)win_to_nat(row) * N;
        else          orow = (size_t)row * N;
        #pragma unroll
        for (int j = 0; j < 8; j++) {
            int col = col0 + j;
            float v = acc[i][j] + bias[col];
            if (EPI == 1) v = 0.5f * v * (1.0f + erff(v * 0.70710678118654752f));
            if (EPI == 2 || EPI == 3) v += resid[orow + col];
            C[orow + col] = v;
        }
    }
}

// ---------------------------------------------------------------------------
// Windowed attention. One block per (window, head): 2048*12 = 24576 blocks,
// 256 threads = 8 warps, each warp owns rows n = warp, warp+8, ...
// Fuses: q*scale, q@k^T, relative-position bias, shifted-window mask,
// softmax, @v. Output in window order, (rw, head*32+d).
// ---------------------------------------------------------------------------
__global__ __launch_bounds__(256)
void attn_kernel(const float* __restrict__ qkv, const float* __restrict__ rpb,
                 float* __restrict__ out) {
    const float SCALE = 0.17677669529663687f;  // 1/sqrt(32)

    int blk = blockIdx.x;
    int bw = blk / HEADS, head = blk - bw * HEADS;
    int w = bw & 63;
    int wh = w >> 3, ww = w & 7;

    __shared__ float qs[49][33], ks[49][33], vs[49][33];
    __shared__ float prow[8][56];
    __shared__ int   cnt[49];

    const float* base = qkv + (size_t)(bw * NWIN) * QKVN + head * HD;
    int t = threadIdx.x;

    for (int i = t; i < 49 * 32; i += 256) {
        int n = i >> 5, d = i & 31;
        const float* p = base + (size_t)n * QKVN + d;
        qs[n][d] = p[0];
        ks[n][d] = p[384];
        vs[n][d] = p[768];
    }
    if (t < 49) {
        int r = t / 7, c = t - (t / 7) * 7;
        int hs = wh * 7 + r, wsq = ww * 7 + c;
        int rh  = hs  < 49 ? 0 : (hs  < 53 ? 1 : 2);
        int rw_ = wsq < 49 ? 0 : (wsq < 53 ? 1 : 2);
        cnt[t] = rh * 3 + rw_;
    }
    __syncthreads();

    int warp = t >> 5, lane = t & 31;

    for (int n = warp; n < 49; n += 8) {
        int m0 = lane, m1 = lane + 32;
        bool has1 = (m1 < 49);
        float s0 = 0.0f, s1 = 0.0f;
        #pragma unroll 8
        for (int d = 0; d < 32; d++) {
            float qd = qs[n][d];
            s0 = fmaf(qd, ks[m0][d], s0);
            if (has1) s1 = fmaf(qd, ks[m1][d], s1);
        }
        int r1 = n / 7, c1 = n - r1 * 7;
        {
            int r2 = m0 / 7, c2 = m0 - r2 * 7;
            int idx = (r1 - r2 + 6) * 13 + (c1 - c2 + 6);
            s0 = s0 * SCALE + rpb[idx * HEADS + head]
               + (cnt[n] != cnt[m0] ? -100.0f : 0.0f);
        }
        if (has1) {
            int r2 = m1 / 7, c2 = m1 - r2 * 7;
            int idx = (r1 - r2 + 6) * 13 + (c1 - c2 + 6);
            s1 = s1 * SCALE + rpb[idx * HEADS + head]
               + (cnt[n] != cnt[m1] ? -100.0f : 0.0f);
        } else {
            s1 = -1e30f;
        }

        float mx = fmaxf(s0, s1);
        #pragma unroll
        for (int o = 16; o; o >>= 1) mx = fmaxf(mx, __shfl_xor_sync(FULLM, mx, o));
        float e0 = __expf(s0 - mx);
        float e1 = has1 ? __expf(s1 - mx) : 0.0f;
        float sum = e0 + e1;
        #pragma unroll
        for (int o = 16; o; o >>= 1) sum += __shfl_xor_sync(FULLM, sum, o);
        float inv = 1.0f / sum;

        prow[warp][m0] = e0 * inv;
        if (has1) prow[warp][m1] = e1 * inv;
        __syncwarp();

        float o = 0.0f;
        #pragma unroll 7
        for (int m = 0; m < 49; m++) o = fmaf(prow[warp][m], vs[m][lane], o);
        out[(size_t)(bw * NWIN + n) * CDIM + head * HD + lane] = o;
        __syncwarp();
    }
}

// ---------------------------------------------------------------------------
// Host launch
// ---------------------------------------------------------------------------
extern "C" void kernel_launch(void* const* d_in, const int* in_sizes, int n_in,
                              void* d_out, int out_size) {
    const float* x       = (const float*)d_in[0];
    const float* norm1_w = (const float*)d_in[1];
    const float* norm1_b = (const float*)d_in[2];
    const float* qkv_w   = (const float*)d_in[3];
    const float* qkv_b   = (const float*)d_in[4];
    const float* rpb     = (const float*)d_in[5];
    const float* proj_w  = (const float*)d_in[6];
    const float* proj_b  = (const float*)d_in[7];
    const float* norm2_w = (const float*)d_in[8];
    const float* norm2_b = (const float*)d_in[9];
    const float* fc1_w   = (const float*)d_in[10];
    const float* fc1_b   = (const float*)d_in[11];
    const float* fc2_w   = (const float*)d_in[12];
    const float* fc2_b   = (const float*)d_in[13];
    // d_in[14], d_in[15]: H, W (static 56x56; unused)

    float *p_xw, *p_qkv, *p_attn, *p_xnew, *p_yn, *p_hid;
    cudaGetSymbolAddress((void**)&p_xw,   g_xw);
    cudaGetSymbolAddress((void**)&p_qkv,  g_qkv);
    cudaGetSymbolAddress((void**)&p_attn, g_attn);
    cudaGetSymbolAddress((void**)&p_xnew, g_xnew);
    cudaGetSymbolAddress((void**)&p_yn,   g_yn);
    cudaGetSymbolAddress((void**)&p_hid,  g_hid);

    float* out = (float*)d_out;

    // 1. LN1 fused with shift+window gather -> window-order rows
    ln_kernel<1><<<T_TOK, 128>>>(x, norm1_w, norm1_b, p_xw);

    // 2. qkv = xw @ qkv_w + b  [100352 x 1152]
    sgemm_kernel<0><<<dim3(QKVN / 128, T_TOK / 128), 256>>>(
        p_xw, qkv_w, qkv_b, nullptr, p_qkv, T_TOK, QKVN, CDIM);

    // 3. windowed attention (bias + mask + softmax + @v)
    attn_kernel<<<BW * HEADS, 256>>>(p_qkv, rpb, p_attn);

    // 4. proj + window-reverse + unshift + residual -> natural order
    sgemm_kernel<2><<<dim3(CDIM / 128, T_TOK / 128), 256>>>(
        p_attn, proj_w, proj_b, x, p_xnew, T_TOK, CDIM, CDIM);

    // 5. LN2
    ln_kernel<0><<<T_TOK, 128>>>(p_xnew, norm2_w, norm2_b, p_yn);

    // 6. fc1 + exact GELU
    sgemm_kernel<1><<<dim3(HID / 128, T_TOK / 128), 256>>>(
        p_yn, fc1_w, fc1_b, nullptr, p_hid, T_TOK, HID, CDIM);

    // 7. fc2 + residual -> final output
    sgemm_kernel<3><<<dim3(CDIM / 128, T_TOK / 128), 256>>>(
        p_hid, fc2_w, fc2_b, p_xnew, out, T_TOK, CDIM, HID);
}

// round 6
// speedup vs baseline: 1.3309x; 1.3309x over previous
#include <cuda_runtime.h>
#include <cuda_bf16.h>
#include <math.h>
#include <cstdint>

// ---------------------------------------------------------------------------
// Swin Transformer block. GEMMs via mma.sync tf32 (3xTF32 compensated) —
// baseline sm_103 target (no 'a' features available in this toolchain).
// B=32, H=W=56, C=384, heads=12, hd=32, window=7, shift=3.
// ---------------------------------------------------------------------------

#define T_TOK   100352
#define CDIM    384
#define HID     1536
#define QKVN    1152
#define BW      2048
#define NWIN    49
#define HEADS   12
#define HD      32
#define FULLM   0xffffffffu

// scratch (device globals: allocation-guard-safe)
__device__ float g_xw  [(size_t)T_TOK * CDIM];
__device__ float g_qkv [(size_t)T_TOK * QKVN];
__device__ float g_attn[(size_t)T_TOK * CDIM];
__device__ float g_xnew[(size_t)T_TOK * CDIM];
__device__ float g_yn  [(size_t)T_TOK * CDIM];
__device__ float g_hid [(size_t)T_TOK * HID];

// ---------------------------------------------------------------------------
// index map: window-order row -> natural-order row (roll + partition fused)
// ---------------------------------------------------------------------------
__device__ __forceinline__ int win_to_nat(int rw) {
    int bw = rw / NWIN, n = rw - bw * NWIN;
    int b  = bw >> 6,  w  = bw & 63;
    int wh = w >> 3,   ww = w & 7;
    int r  = n / 7,    c  = n - r * 7;
    int h0 = wh * 7 + r + 3; if (h0 >= 56) h0 -= 56;
    int w0 = ww * 7 + c + 3; if (w0 >= 56) w0 -= 56;
    return b * 3136 + h0 * 56 + w0;
}

// m16n8k8 tf32 mma.sync, D += A*B (fp32 accum)
#define MMA_TF32(d, a, b) \
    asm volatile("mma.sync.aligned.m16n8k8.row.col.f32.tf32.tf32.f32 " \
        "{%0,%1,%2,%3}, {%4,%5,%6,%7}, {%8,%9}, {%0,%1,%2,%3};" \
        : "+f"((d)[0]), "+f"((d)[1]), "+f"((d)[2]), "+f"((d)[3]) \
        : "r"((a)[0]), "r"((a)[1]), "r"((a)[2]), "r"((a)[3]), \
          "r"((b)[0]), "r"((b)[1]))

// tf32 split: hi = a with low 13 mantissa bits cleared (exact tf32);
// lo = a - hi (exact in fp32; HW truncates to tf32 on use, err ~2^-24 of a)
__device__ __forceinline__ void tf32_split_u(float v, uint32_t& hi, uint32_t& lo) {
    uint32_t h = __float_as_uint(v) & 0xFFFFE000u;
    hi = h;
    lo = __float_as_uint(v - __uint_as_float(h));
}

// ---------------------------------------------------------------------------
// GEMM: C[M,N] = A[M,K] @ W[K,N] (+epilogue), tf32x3 via mma.sync.
// Tile 128x128, BK=16, 256 threads (4x2 warps, warp tile 32x64),
// double-buffered smem, hoisted LDGs, 1 syncthreads/stage.
// EPI 0: +bias    EPI 1: gelu(+bias)
// EPI 2: scatter win_to_nat + resid    EPI 3: +resid
// ---------------------------------------------------------------------------
#define BKG 16

template <int EPI>
__global__ __launch_bounds__(256)
void gemm_mma(const float* __restrict__ A, const float* __restrict__ Wm,
              const float* __restrict__ bias, const float* __restrict__ resid,
              float* __restrict__ C, int M, int N, int K) {
    __shared__ float As[2][128][20];    // [row][k], stride 20: frag loads conflict-free
    __shared__ float Bs[2][BKG][136];   // [k][n],  stride 136: frag loads conflict-free

    int t = threadIdx.x, lane = t & 31;
    int wid = t >> 5;
    int wm = wid & 3, wn = wid >> 2;    // warp grid 4(m) x 2(n)
    int g = lane >> 2, q = lane & 3;
    int bx = blockIdx.x, by = blockIdx.y;

    const float* Ab = A  + (size_t)(by * 128) * K;
    const float* Bb = Wm + (size_t)(bx * 128);

    int a_row = t >> 2;            // 0..63  (+64 for second chunk)
    int a_c4  = (t & 3) * 4;       // 0,4,8,12
    int b_k   = t >> 5;            // 0..7   (+8 for second chunk)
    int b_n4  = (t & 31) * 4;      // 0..124

    float acc[2][8][4];
    #pragma unroll
    for (int mt = 0; mt < 2; mt++)
        #pragma unroll
        for (int nt = 0; nt < 8; nt++)
            #pragma unroll
            for (int j = 0; j < 4; j++) acc[mt][nt][j] = 0.0f;

    // prologue: stage 0 -> buffer 0
    {
        float4 av0 = *(const float4*)(Ab + (size_t)a_row * K + a_c4);
        float4 av1 = *(const float4*)(Ab + (size_t)(a_row + 64) * K + a_c4);
        float4 bv0 = *(const float4*)(Bb + (size_t)b_k * N + b_n4);
        float4 bv1 = *(const float4*)(Bb + (size_t)(b_k + 8) * N + b_n4);
        *(float4*)&As[0][a_row][a_c4]      = av0;
        *(float4*)&As[0][a_row + 64][a_c4] = av1;
        *(float4*)&Bs[0][b_k][b_n4]        = bv0;
        *(float4*)&Bs[0][b_k + 8][b_n4]    = bv1;
    }
    __syncthreads();

    int S = K / BKG;
    for (int s = 0; s < S; s++) {
        int b = s & 1;
        bool more = (s + 1) < S;
        float4 av0, av1, bv0, bv1;
        if (more) {
            int k0 = (s + 1) * BKG;
            av0 = *(const float4*)(Ab + (size_t)a_row * K + k0 + a_c4);
            av1 = *(const float4*)(Ab + (size_t)(a_row + 64) * K + k0 + a_c4);
            bv0 = *(const float4*)(Bb + (size_t)(k0 + b_k) * N + b_n4);
            bv1 = *(const float4*)(Bb + (size_t)(k0 + b_k + 8) * N + b_n4);
        }

        #pragma unroll
        for (int kk = 0; kk < BKG; kk += 8) {
            uint32_t ahi[2][4], alo[2][4];
            #pragma unroll
            for (int mt = 0; mt < 2; mt++) {
                int r0 = wm * 32 + mt * 16;
                float a0 = As[b][r0 + g][kk + q];
                float a1 = As[b][r0 + g + 8][kk + q];
                float a2 = As[b][r0 + g][kk + q + 4];
                float a3 = As[b][r0 + g + 8][kk + q + 4];
                tf32_split_u(a0, ahi[mt][0], alo[mt][0]);
                tf32_split_u(a1, ahi[mt][1], alo[mt][1]);
                tf32_split_u(a2, ahi[mt][2], alo[mt][2]);
                tf32_split_u(a3, ahi[mt][3], alo[mt][3]);
            }
            uint32_t bhi[8][2], blo[8][2];
            #pragma unroll
            for (int nt = 0; nt < 8; nt++) {
                int c0 = wn * 64 + nt * 8;
                float b0 = Bs[b][kk + q][c0 + g];
                float b1 = Bs[b][kk + q + 4][c0 + g];
                tf32_split_u(b0, bhi[nt][0], blo[nt][0]);
                tf32_split_u(b1, bhi[nt][1], blo[nt][1]);
            }
            #pragma unroll
            for (int mt = 0; mt < 2; mt++)
                #pragma unroll
                for (int nt = 0; nt < 8; nt++) {
                    MMA_TF32(acc[mt][nt], ahi[mt], bhi[nt]);
                    MMA_TF32(acc[mt][nt], ahi[mt], blo[nt]);
                    MMA_TF32(acc[mt][nt], alo[mt], bhi[nt]);
                }
        }

        if (more) {
            int nb = b ^ 1;
            *(float4*)&As[nb][a_row][a_c4]      = av0;
            *(float4*)&As[nb][a_row + 64][a_c4] = av1;
            *(float4*)&Bs[nb][b_k][b_n4]        = bv0;
            *(float4*)&Bs[nb][b_k + 8][b_n4]    = bv1;
            __syncthreads();
        }
    }

    // Epilogue: fragment layout -> float2 stores.
    // c0,c1: (row, col..col+1); c2,c3: (row+8, ...)
    #pragma unroll
    for (int nt = 0; nt < 8; nt++) {
        int col = bx * 128 + wn * 64 + nt * 8 + q * 2;
        float bx0 = bias[col], bx1 = bias[col + 1];
        #pragma unroll
        for (int mt = 0; mt < 2; mt++) {
            int row = by * 128 + wm * 32 + mt * 16 + g;
            #pragma unroll
            for (int h = 0; h < 2; h++) {       // h=0: row, h=1: row+8
                int rr = row + h * 8;
                size_t orow = (EPI == 2) ? (size_t)win_to_nat(rr) * N
                                         : (size_t)rr * N;
                float v0 = acc[mt][nt][h * 2 + 0] + bx0;
                float v1 = acc[mt][nt][h * 2 + 1] + bx1;
                if (EPI == 1) {
                    v0 = 0.5f * v0 * (1.0f + erff(v0 * 0.70710678118654752f));
                    v1 = 0.5f * v1 * (1.0f + erff(v1 * 0.70710678118654752f));
                }
                if (EPI == 2 || EPI == 3) {
                    float2 rv = *(const float2*)(resid + orow + col);
                    v0 += rv.x; v1 += rv.y;
                }
                float2 ov; ov.x = v0; ov.y = v1;
                *(float2*)(C + orow + col) = ov;
            }
        }
    }
}

// ---------------------------------------------------------------------------
// LayerNorm over C=384. GATHER=1 fuses roll+window_partition gather.
// ---------------------------------------------------------------------------
template <int GATHER>
__global__ void ln_kernel(const float* __restrict__ x,
                          const float* __restrict__ w,
                          const float* __restrict__ b,
                          float* __restrict__ out) {
    int rw = blockIdx.x;
    int g  = GATHER ? win_to_nat(rw) : rw;
    const float* xr = x + (size_t)g * CDIM;
    int t = threadIdx.x;

    float v0 = xr[t], v1 = xr[t + 128], v2 = xr[t + 256];
    float s  = v0 + v1 + v2;
    float sq = v0 * v0 + v1 * v1 + v2 * v2;

    #pragma unroll
    for (int o = 16; o; o >>= 1) {
        s  += __shfl_xor_sync(FULLM, s,  o);
        sq += __shfl_xor_sync(FULLM, sq, o);
    }
    __shared__ float ssum[4], ssq[4];
    int warp = t >> 5, lane = t & 31;
    if (!lane) { ssum[warp] = s; ssq[warp] = sq; }
    __syncthreads();
    s  = ssum[0] + ssum[1] + ssum[2] + ssum[3];
    sq = ssq[0]  + ssq[1]  + ssq[2]  + ssq[3];

    float m    = s * (1.0f / CDIM);
    float var  = sq * (1.0f / CDIM) - m * m;
    float rstd = rsqrtf(var + 1e-5f);

    float* o = out + (size_t)rw * CDIM;
    o[t]       = (v0 - m) * rstd * w[t]       + b[t];
    o[t + 128] = (v1 - m) * rstd * w[t + 128] + b[t + 128];
    o[t + 256] = (v2 - m) * rstd * w[t + 256] + b[t + 256];
}

// ---------------------------------------------------------------------------
// Windowed attention: one block per (window, head).
// ---------------------------------------------------------------------------
__global__ __launch_bounds__(256)
void attn_kernel(const float* __restrict__ qkv, const float* __restrict__ rpb,
                 float* __restrict__ out) {
    const float SCALE = 0.17677669529663687f;  // 1/sqrt(32)

    int blk = blockIdx.x;
    int bw = blk / HEADS, head = blk - bw * HEADS;
    int w = bw & 63;
    int wh = w >> 3, ww = w & 7;

    __shared__ float qs[49][33], ks[49][33], vs[49][33];
    __shared__ float prow[8][56];
    __shared__ int   cnt[49];

    const float* base = qkv + (size_t)(bw * NWIN) * QKVN + head * HD;
    int t = threadIdx.x;

    for (int i = t; i < 49 * 32; i += 256) {
        int n = i >> 5, d = i & 31;
        const float* p = base + (size_t)n * QKVN + d;
        qs[n][d] = p[0];
        ks[n][d] = p[384];
        vs[n][d] = p[768];
    }
    if (t < 49) {
        int r = t / 7, c = t - (t / 7) * 7;
        int hs = wh * 7 + r, wsq = ww * 7 + c;
        int rh  = hs  < 49 ? 0 : (hs  < 53 ? 1 : 2);
        int rw_ = wsq < 49 ? 0 : (wsq < 53 ? 1 : 2);
        cnt[t] = rh * 3 + rw_;
    }
    __syncthreads();

    int warp = t >> 5, lane = t & 31;

    for (int n = warp; n < 49; n += 8) {
        int m0 = lane, m1 = lane + 32;
        bool has1 = (m1 < 49);
        float s0 = 0.0f, s1 = 0.0f;
        #pragma unroll 8
        for (int d = 0; d < 32; d++) {
            float qd = qs[n][d];
            s0 = fmaf(qd, ks[m0][d], s0);
            if (has1) s1 = fmaf(qd, ks[m1][d], s1);
        }
        int r1 = n / 7, c1 = n - r1 * 7;
        {
            int r2 = m0 / 7, c2 = m0 - r2 * 7;
            int idx = (r1 - r2 + 6) * 13 + (c1 - c2 + 6);
            s0 = s0 * SCALE + rpb[idx * HEADS + head]
               + (cnt[n] != cnt[m0] ? -100.0f : 0.0f);
        }
        if (has1) {
            int r2 = m1 / 7, c2 = m1 - r2 * 7;
            int idx = (r1 - r2 + 6) * 13 + (c1 - c2 + 6);
            s1 = s1 * SCALE + rpb[idx * HEADS + head]
               + (cnt[n] != cnt[m1] ? -100.0f : 0.0f);
        } else {
            s1 = -1e30f;
        }

        float mx = fmaxf(s0, s1);
        #pragma unroll
        for (int o = 16; o; o >>= 1) mx = fmaxf(mx, __shfl_xor_sync(FULLM, mx, o));
        float e0 = __expf(s0 - mx);
        float e1 = has1 ? __expf(s1 - mx) : 0.0f;
        float sum = e0 + e1;
        #pragma unroll
        for (int o = 16; o; o >>= 1) sum += __shfl_xor_sync(FULLM, sum, o);
        float inv = 1.0f / sum;

        prow[warp][m0] = e0 * inv;
        if (has1) prow[warp][m1] = e1 * inv;
        __syncwarp();

        float o = 0.0f;
        #pragma unroll 7
        for (int m = 0; m < 49; m++) o = fmaf(prow[warp][m], vs[m][lane], o);
        out[(size_t)(bw * NWIN + n) * CDIM + head * HD + lane] = o;
        __syncwarp();
    }
}

// ---------------------------------------------------------------------------
// Host launch
// ---------------------------------------------------------------------------
extern "C" void kernel_launch(void* const* d_in, const int* in_sizes, int n_in,
                              void* d_out, int out_size) {
    const float* x       = (const float*)d_in[0];
    const float* norm1_w = (const float*)d_in[1];
    const float* norm1_b = (const float*)d_in[2];
    const float* qkv_w   = (const float*)d_in[3];
    const float* qkv_b   = (const float*)d_in[4];
    const float* rpb     = (const float*)d_in[5];
    const float* proj_w  = (const float*)d_in[6];
    const float* proj_b  = (const float*)d_in[7];
    const float* norm2_w = (const float*)d_in[8];
    const float* norm2_b = (const float*)d_in[9];
    const float* fc1_w   = (const float*)d_in[10];
    const float* fc1_b   = (const float*)d_in[11];
    const float* fc2_w   = (const float*)d_in[12];
    const float* fc2_b   = (const float*)d_in[13];

    float *p_xw, *p_qkv, *p_attn, *p_xnew, *p_yn, *p_hid;
    cudaGetSymbolAddress((void**)&p_xw,   g_xw);
    cudaGetSymbolAddress((void**)&p_qkv,  g_qkv);
    cudaGetSymbolAddress((void**)&p_attn, g_attn);
    cudaGetSymbolAddress((void**)&p_xnew, g_xnew);
    cudaGetSymbolAddress((void**)&p_yn,   g_yn);
    cudaGetSymbolAddress((void**)&p_hid,  g_hid);

    float* out = (float*)d_out;

    // 1. LN1 fused with shift+window gather -> window-order rows
    ln_kernel<1><<<T_TOK, 128>>>(x, norm1_w, norm1_b, p_xw);

    // 2. qkv = xw @ qkv_w + b
    gemm_mma<0><<<dim3(QKVN / 128, T_TOK / 128), 256>>>(
        p_xw, qkv_w, qkv_b, nullptr, p_qkv, T_TOK, QKVN, CDIM);

    // 3. windowed attention
    attn_kernel<<<BW * HEADS, 256>>>(p_qkv, rpb, p_attn);

    // 4. proj + window-reverse + unshift + residual
    gemm_mma<2><<<dim3(CDIM / 128, T_TOK / 128), 256>>>(
        p_attn, proj_w, proj_b, x, p_xnew, T_TOK, CDIM, CDIM);

    // 5. LN2
    ln_kernel<0><<<T_TOK, 128>>>(p_xnew, norm2_w, norm2_b, p_yn);

    // 6. fc1 + exact GELU
    gemm_mma<1><<<dim3(HID / 128, T_TOK / 128), 256>>>(
        p_yn, fc1_w, fc1_b, nullptr, p_hid, T_TOK, HID, CDIM);

    // 7. fc2 + residual -> final output
    gemm_mma<3><<<dim3(CDIM / 128, T_TOK / 128), 256>>>(
        p_hid, fc2_w, fc2_b, p_xnew, out, T_TOK, CDIM, HID);
}

// round 13
// speedup vs baseline: 1.5137x; 1.1373x over previous
#include <cuda_runtime.h>
#include <cuda_bf16.h>
#include <math.h>
#include <cstdint>

// ---------------------------------------------------------------------------
// Swin Transformer block. GEMMs via mma.sync tf32 (3xTF32 compensated),
// cp.async.cg double-buffered pipeline, 2 CTAs/SM.
// B=32, H=W=56, C=384, heads=12, hd=32, window=7, shift=3.
// ---------------------------------------------------------------------------

#define T_TOK   100352
#define CDIM    384
#define HID     1536
#define QKVN    1152
#define BW      2048
#define NWIN    49
#define HEADS   12
#define HD      32
#define FULLM   0xffffffffu

// scratch (device globals: allocation-guard-safe)
__device__ float g_xw  [(size_t)T_TOK * CDIM];
__device__ float g_qkv [(size_t)T_TOK * QKVN];
__device__ float g_attn[(size_t)T_TOK * CDIM];
__device__ float g_xnew[(size_t)T_TOK * CDIM];
__device__ float g_yn  [(size_t)T_TOK * CDIM];
__device__ float g_hid [(size_t)T_TOK * HID];

__device__ __forceinline__ uint32_t smem_u32(const void* p) {
    uint32_t a;
    asm("{ .reg .u64 tmp; cvta.to.shared.u64 tmp, %1; cvt.u32.u64 %0, tmp; }"
        : "=r"(a) : "l"(p));
    return a;
}
__device__ __forceinline__ void cp_async16(uint32_t dst, const void* src) {
    asm volatile("cp.async.cg.shared.global [%0], [%1], 16;" :: "r"(dst), "l"(src));
}
#define CP_COMMIT() asm volatile("cp.async.commit_group;" ::: "memory")
#define CP_WAIT(n)  asm volatile("cp.async.wait_group %0;" :: "n"(n) : "memory")

// ---------------------------------------------------------------------------
// index map: window-order row -> natural-order row (roll + partition fused)
// ---------------------------------------------------------------------------
__device__ __forceinline__ int win_to_nat(int rw) {
    int bw = rw / NWIN, n = rw - bw * NWIN;
    int b  = bw >> 6,  w  = bw & 63;
    int wh = w >> 3,   ww = w & 7;
    int r  = n / 7,    c  = n - r * 7;
    int h0 = wh * 7 + r + 3; if (h0 >= 56) h0 -= 56;
    int w0 = ww * 7 + c + 3; if (w0 >= 56) w0 -= 56;
    return b * 3136 + h0 * 56 + w0;
}

// m16n8k8 tf32 mma.sync, D += A*B (fp32 accum)
#define MMA_TF32(d, a, b) \
    asm volatile("mma.sync.aligned.m16n8k8.row.col.f32.tf32.tf32.f32 " \
        "{%0,%1,%2,%3}, {%4,%5,%6,%7}, {%8,%9}, {%0,%1,%2,%3};" \
        : "+f"((d)[0]), "+f"((d)[1]), "+f"((d)[2]), "+f"((d)[3]) \
        : "r"((a)[0]), "r"((a)[1]), "r"((a)[2]), "r"((a)[3]), \
          "r"((b)[0]), "r"((b)[1]))

__device__ __forceinline__ void tf32_split_u(float v, uint32_t& hi, uint32_t& lo) {
    uint32_t h = __float_as_uint(v) & 0xFFFFE000u;
    hi = h;
    lo = __float_as_uint(v - __uint_as_float(h));
}

// ---------------------------------------------------------------------------
// GEMM: C[M,N] = A[M,K] @ W[K,N] (+epilogue), tf32x3 via mma.sync.
// Tile 128x128, BK=16, 256 threads (4x2 warps, warp tile 32x64),
// cp.async 2-stage pipeline, 2 CTAs/SM.
// EPI 0: +bias    EPI 1: gelu(+bias)
// EPI 2: scatter win_to_nat + resid    EPI 3: +resid
// ---------------------------------------------------------------------------
#define BKG 16

template <int EPI>
__global__ __launch_bounds__(256, 2)
void gemm_mma(const float* __restrict__ A, const float* __restrict__ Wm,
              const float* __restrict__ bias, const float* __restrict__ resid,
              float* __restrict__ C, int M, int N, int K) {
    __shared__ float As[2][128][20];    // [row][k], stride 20: frag loads conflict-free
    __shared__ float Bs[2][BKG][136];   // [k][n],  stride 136: frag loads conflict-free

    int t = threadIdx.x, lane = t & 31;
    int wid = t >> 5;
    int wm = wid & 3, wn = wid >> 2;    // warp grid 4(m) x 2(n)
    int g = lane >> 2, q = lane & 3;
    int bx = blockIdx.x, by = blockIdx.y;

    const float* Ab = A  + (size_t)(by * 128) * K;
    const float* Bb = Wm + (size_t)(bx * 128);

    int a_row = t >> 2;            // 0..63  (+64 second chunk)
    int a_c4  = (t & 3) * 4;       // 0,4,8,12
    int b_k   = t >> 5;            // 0..7   (+8 second chunk)
    int b_n4  = (t & 31) * 4;      // 0..124

    // per-thread cp.async smem destinations (byte addresses)
    uint32_t dA0 = smem_u32(&As[0][a_row][a_c4]);
    uint32_t dA1 = smem_u32(&As[0][a_row + 64][a_c4]);
    uint32_t dB0 = smem_u32(&Bs[0][b_k][b_n4]);
    uint32_t dB1 = smem_u32(&Bs[0][b_k + 8][b_n4]);
    const uint32_t strideA = 128 * 20 * 4;   // buffer stride in As
    const uint32_t strideB = BKG * 136 * 4;  // buffer stride in Bs

    const float* gA0 = Ab + (size_t)a_row * K + a_c4;
    const float* gA1 = Ab + (size_t)(a_row + 64) * K + a_c4;
    const float* gB0 = Bb + (size_t)b_k * N + b_n4;
    const float* gB1 = Bb + (size_t)(b_k + 8) * N + b_n4;

    float acc[2][8][4];
    #pragma unroll
    for (int mt = 0; mt < 2; mt++)
        #pragma unroll
        for (int nt = 0; nt < 8; nt++)
            #pragma unroll
            for (int j = 0; j < 4; j++) acc[mt][nt][j] = 0.0f;

    // prologue: stage 0 -> buffer 0
    cp_async16(dA0, gA0);
    cp_async16(dA1, gA1);
    cp_async16(dB0, gB0);
    cp_async16(dB1, gB1);
    CP_COMMIT();

    int S = K / BKG;
    for (int s = 0; s < S; s++) {
        int b = s & 1;
        if (s + 1 < S) {                    // issue next stage into buf b^1
            int k0 = (s + 1) * BKG;
            uint32_t nb = (uint32_t)(b ^ 1);
            cp_async16(dA0 + nb * strideA, gA0 + k0);
            cp_async16(dA1 + nb * strideA, gA1 + k0);
            cp_async16(dB0 + nb * strideB, gB0 + (size_t)k0 * N);
            cp_async16(dB1 + nb * strideB, gB1 + (size_t)k0 * N);
            CP_COMMIT();
            CP_WAIT(1);                     // stage s complete, s+1 in flight
        } else {
            CP_WAIT(0);
        }
        __syncthreads();

        #pragma unroll
        for (int kk = 0; kk < BKG; kk += 8) {
            uint32_t ahi[2][4], alo[2][4];
            #pragma unroll
            for (int mt = 0; mt < 2; mt++) {
                int r0 = wm * 32 + mt * 16;
                float a0 = As[b][r0 + g][kk + q];
                float a1 = As[b][r0 + g + 8][kk + q];
                float a2 = As[b][r0 + g][kk + q + 4];
                float a3 = As[b][r0 + g + 8][kk + q + 4];
                tf32_split_u(a0, ahi[mt][0], alo[mt][0]);
                tf32_split_u(a1, ahi[mt][1], alo[mt][1]);
                tf32_split_u(a2, ahi[mt][2], alo[mt][2]);
                tf32_split_u(a3, ahi[mt][3], alo[mt][3]);
            }
            #pragma unroll
            for (int nt = 0; nt < 8; nt++) {
                int c0 = wn * 64 + nt * 8;
                uint32_t bh[2], bl[2];
                float b0 = Bs[b][kk + q][c0 + g];
                float b1 = Bs[b][kk + q + 4][c0 + g];
                tf32_split_u(b0, bh[0], bl[0]);
                tf32_split_u(b1, bh[1], bl[1]);
                #pragma unroll
                for (int mt = 0; mt < 2; mt++) {
                    MMA_TF32(acc[mt][nt], ahi[mt], bh);
                    MMA_TF32(acc[mt][nt], ahi[mt], bl);
                    MMA_TF32(acc[mt][nt], alo[mt], bh);
                }
            }
        }
        __syncthreads();    // compute done before buf b is overwritten next iter
    }

    // Epilogue: fragment layout -> float2 stores.
    #pragma unroll
    for (int nt = 0; nt < 8; nt++) {
        int col = bx * 128 + wn * 64 + nt * 8 + q * 2;
        float bx0 = bias[col], bx1 = bias[col + 1];
        #pragma unroll
        for (int mt = 0; mt < 2; mt++) {
            int row = by * 128 + wm * 32 + mt * 16 + g;
            #pragma unroll
            for (int h = 0; h < 2; h++) {       // h=0: row, h=1: row+8
                int rr = row + h * 8;
                size_t orow = (EPI == 2) ? (size_t)win_to_nat(rr) * N
                                         : (size_t)rr * N;
                float v0 = acc[mt][nt][h * 2 + 0] + bx0;
                float v1 = acc[mt][nt][h * 2 + 1] + bx1;
                if (EPI == 1) {
                    v0 = 0.5f * v0 * (1.0f + erff(v0 * 0.70710678118654752f));
                    v1 = 0.5f * v1 * (1.0f + erff(v1 * 0.70710678118654752f));
                }
                if (EPI == 2 || EPI == 3) {
                    float2 rv = *(const float2*)(resid + orow + col);
                    v0 += rv.x; v1 += rv.y;
                }
                float2 ov; ov.x = v0; ov.y = v1;
                *(float2*)(C + orow + col) = ov;
            }
        }
    }
}

// ---------------------------------------------------------------------------
// LayerNorm over C=384. GATHER=1 fuses roll+window_partition gather.
// ---------------------------------------------------------------------------
template <int GATHER>
__global__ void ln_kernel(const float* __restrict__ x,
                          const float* __restrict__ w,
                          const float* __restrict__ b,
                          float* __restrict__ out) {
    int rw = blockIdx.x;
    int g  = GATHER ? win_to_nat(rw) : rw;
    const float* xr = x + (size_t)g * CDIM;
    int t = threadIdx.x;

    float v0 = xr[t], v1 = xr[t + 128], v2 = xr[t + 256];
    float s  = v0 + v1 + v2;
    float sq = v0 * v0 + v1 * v1 + v2 * v2;

    #pragma unroll
    for (int o = 16; o; o >>= 1) {
        s  += __shfl_xor_sync(FULLM, s,  o);
        sq += __shfl_xor_sync(FULLM, sq, o);
    }
    __shared__ float ssum[4], ssq[4];
    int warp = t >> 5, lane = t & 31;
    if (!lane) { ssum[warp] = s; ssq[warp] = sq; }
    __syncthreads();
    s  = ssum[0] + ssum[1] + ssum[2] + ssum[3];
    sq = ssq[0]  + ssq[1]  + ssq[2]  + ssq[3];

    float m    = s * (1.0f / CDIM);
    float var  = sq * (1.0f / CDIM) - m * m;
    float rstd = rsqrtf(var + 1e-5f);

    float* o = out + (size_t)rw * CDIM;
    o[t]       = (v0 - m) * rstd * w[t]       + b[t];
    o[t + 128] = (v1 - m) * rstd * w[t + 128] + b[t + 128];
    o[t + 256] = (v2 - m) * rstd * w[t + 256] + b[t + 256];
}

// ---------------------------------------------------------------------------
// Windowed attention: one block per (window, head).
// ---------------------------------------------------------------------------
__global__ __launch_bounds__(256)
void attn_kernel(const float* __restrict__ qkv, const float* __restrict__ rpb,
                 float* __restrict__ out) {
    const float SCALE = 0.17677669529663687f;  // 1/sqrt(32)

    int blk = blockIdx.x;
    int bw = blk / HEADS, head = blk - bw * HEADS;
    int w = bw & 63;
    int wh = w >> 3, ww = w & 7;

    __shared__ float qs[49][33], ks[49][33], vs[49][33];
    __shared__ float prow[8][56];
    __shared__ int   cnt[49];

    const float* base = qkv + (size_t)(bw * NWIN) * QKVN + head * HD;
    int t = threadIdx.x;

    for (int i = t; i < 49 * 32; i += 256) {
        int n = i >> 5, d = i & 31;
        const float* p = base + (size_t)n * QKVN + d;
        qs[n][d] = p[0];
        ks[n][d] = p[384];
        vs[n][d] = p[768];
    }
    if (t < 49) {
        int r = t / 7, c = t - (t / 7) * 7;
        int hs = wh * 7 + r, wsq = ww * 7 + c;
        int rh  = hs  < 49 ? 0 : (hs  < 53 ? 1 : 2);
        int rw_ = wsq < 49 ? 0 : (wsq < 53 ? 1 : 2);
        cnt[t] = rh * 3 + rw_;
    }
    __syncthreads();

    int warp = t >> 5, lane = t & 31;

    for (int n = warp; n < 49; n += 8) {
        int m0 = lane, m1 = lane + 32;
        bool has1 = (m1 < 49);
        float s0 = 0.0f, s1 = 0.0f;
        #pragma unroll 8
        for (int d = 0; d < 32; d++) {
            float qd = qs[n][d];
            s0 = fmaf(qd, ks[m0][d], s0);
            if (has1) s1 = fmaf(qd, ks[m1][d], s1);
        }
        int r1 = n / 7, c1 = n - r1 * 7;
        {
            int r2 = m0 / 7, c2 = m0 - r2 * 7;
            int idx = (r1 - r2 + 6) * 13 + (c1 - c2 + 6);
            s0 = s0 * SCALE + rpb[idx * HEADS + head]
               + (cnt[n] != cnt[m0] ? -100.0f : 0.0f);
        }
        if (has1) {
            int r2 = m1 / 7, c2 = m1 - r2 * 7;
            int idx = (r1 - r2 + 6) * 13 + (c1 - c2 + 6);
            s1 = s1 * SCALE + rpb[idx * HEADS + head]
               + (cnt[n] != cnt[m1] ? -100.0f : 0.0f);
        } else {
            s1 = -1e30f;
        }

        float mx = fmaxf(s0, s1);
        #pragma unroll
        for (int o = 16; o; o >>= 1) mx = fmaxf(mx, __shfl_xor_sync(FULLM, mx, o));
        float e0 = __expf(s0 - mx);
        float e1 = has1 ? __expf(s1 - mx) : 0.0f;
        float sum = e0 + e1;
        #pragma unroll
        for (int o = 16; o; o >>= 1) sum += __shfl_xor_sync(FULLM, sum, o);
        float inv = 1.0f / sum;

        prow[warp][m0] = e0 * inv;
        if (has1) prow[warp][m1] = e1 * inv;
        __syncwarp();

        float o = 0.0f;
        #pragma unroll 7
        for (int m = 0; m < 49; m++) o = fmaf(prow[warp][m], vs[m][lane], o);
        out[(size_t)(bw * NWIN + n) * CDIM + head * HD + lane] = o;
        __syncwarp();
    }
}

// ---------------------------------------------------------------------------
// Host launch
// ---------------------------------------------------------------------------
extern "C" void kernel_launch(void* const* d_in, const int* in_sizes, int n_in,
                              void* d_out, int out_size) {
    const float* x       = (const float*)d_in[0];
    const float* norm1_w = (const float*)d_in[1];
    const float* norm1_b = (const float*)d_in[2];
    const float* qkv_w   = (const float*)d_in[3];
    const float* qkv_b   = (const float*)d_in[4];
    const float* rpb     = (const float*)d_in[5];
    const float* proj_w  = (const float*)d_in[6];
    const float* proj_b  = (const float*)d_in[7];
    const float* norm2_w = (const float*)d_in[8];
    const float* norm2_b = (const float*)d_in[9];
    const float* fc1_w   = (const float*)d_in[10];
    const float* fc1_b   = (const float*)d_in[11];
    const float* fc2_w   = (const float*)d_in[12];
    const float* fc2_b   = (const float*)d_in[13];

    float *p_xw, *p_qkv, *p_attn, *p_xnew, *p_yn, *p_hid;
    cudaGetSymbolAddress((void**)&p_xw,   g_xw);
    cudaGetSymbolAddress((void**)&p_qkv,  g_qkv);
    cudaGetSymbolAddress((void**)&p_attn, g_attn);
    cudaGetSymbolAddress((void**)&p_xnew, g_xnew);
    cudaGetSymbolAddress((void**)&p_yn,   g_yn);
    cudaGetSymbolAddress((void**)&p_hid,  g_hid);

    float* out = (float*)d_out;

    // 1. LN1 fused with shift+window gather -> window-order rows
    ln_kernel<1><<<T_TOK, 128>>>(x, norm1_w, norm1_b, p_xw);

    // 2. qkv = xw @ qkv_w + b
    gemm_mma<0><<<dim3(QKVN / 128, T_TOK / 128), 256>>>(
        p_xw, qkv_w, qkv_b, nullptr, p_qkv, T_TOK, QKVN, CDIM);

    // 3. windowed attention
    attn_kernel<<<BW * HEADS, 256>>>(p_qkv, rpb, p_attn);

    // 4. proj + window-reverse + unshift + residual
    gemm_mma<2><<<dim3(CDIM / 128, T_TOK / 128), 256>>>(
        p_attn, proj_w, proj_b, x, p_xnew, T_TOK, CDIM, CDIM);

    // 5. LN2
    ln_kernel<0><<<T_TOK, 128>>>(p_xnew, norm2_w, norm2_b, p_yn);

    // 6. fc1 + exact GELU
    gemm_mma<1><<<dim3(HID / 128, T_TOK / 128), 256>>>(
        p_yn, fc1_w, fc1_b, nullptr, p_hid, T_TOK, HID, CDIM);

    // 7. fc2 + residual -> final output
    gemm_mma<3><<<dim3(CDIM / 128, T_TOK / 128), 256>>>(
        p_hid, fc2_w, fc2_b, p_xnew, out, T_TOK, CDIM, HID);
}